// round 12
// baseline (speedup 1.0000x reference)
#include <cuda_runtime.h>
#include <cuda_bf16.h>
#include <math.h>
#include <stdint.h>

#define NBR 4
#define Dd 256
#define SDIM 64
#define MEAS 320
#define MH 128
#define RH 64
#define UD 16
#define NOBS 25
#define BSZ 32768
#define HALL 512
#define K2 528
#define N2P 320            // padded output cols of GEMM2 (256 z + 25 yt + pad)
#define TM 64

__device__ __nv_bfloat16 g_W1h[HALL * MEAS];
__device__ __nv_bfloat16 g_W1l[HALL * MEAS];
__device__ float g_M[NBR * Dd * RH];
__device__ float g_Mu[Dd * UD];
__device__ float g_Pf[Dd * HALL];
__device__ float g_zbias[Dd];
__device__ __nv_bfloat16 g_B2h[N2P * K2];
__device__ __nv_bfloat16 g_B2l[N2P * K2];
__device__ float g_bias2[N2P];

// ---- smem layout (bytes) ----
#define HSTR 1072
#define HP   68608                 // 64*1072
#define OFF_BB 137216              // B tiles: 2 bufs x (2 planes x 320 rows x 48B)
#define BBUF 30720
#define BPL  15360
#define OFF_AB 198656              // A tiles: 2 bufs x (2 planes x 64 x 48B)
#define ABUF 6144
#define APL  3072
#define OFF_LN 210944              // LN scratch: 2 x 4 x 64 floats
#define SMEM_TOTAL 212992

#define CPA(dst, src) asm volatile("cp.async.cg.shared.global [%0], [%1], 16;" :: "r"(dst), "l"(src))
#define CPC()  asm volatile("cp.async.commit_group;")
#define CPW1() asm volatile("cp.async.wait_group 1;")
#define CPW0() asm volatile("cp.async.wait_group 0;")

#define LDSM4(r, a) \
    asm volatile("ldmatrix.sync.aligned.m8n8.x4.shared.b16 {%0,%1,%2,%3}, [%4];" \
        : "=r"((r)[0]), "=r"((r)[1]), "=r"((r)[2]), "=r"((r)[3]) : "r"(a))

__device__ __forceinline__ void mma_bf16(float* d, const uint32_t* a, const uint32_t* b) {
    asm volatile(
        "mma.sync.aligned.m16n8k16.row.col.f32.bf16.bf16.f32 "
        "{%0,%1,%2,%3},{%4,%5,%6,%7},{%8,%9},{%0,%1,%2,%3};\n"
        : "+f"(d[0]), "+f"(d[1]), "+f"(d[2]), "+f"(d[3])
        : "r"(a[0]), "r"(a[1]), "r"(a[2]), "r"(a[3]), "r"(b[0]), "r"(b[1]));
}
__device__ __forceinline__ void split2(float v, __nv_bfloat16& hi, __nv_bfloat16& lo) {
    hi = __float2bfloat16(v);
    lo = __float2bfloat16(v - __bfloat162float(hi));
}
__device__ __forceinline__ uint32_t smem_u32(const void* p) {
    uint32_t a;
    asm("{ .reg .u64 t; cvta.to.shared.u64 t, %1; cvt.u32.u64 %0, t; }" : "=r"(a) : "l"(p));
    return a;
}

// ======================= precompute =======================
__global__ void pre_w1(const float* __restrict__ W1, const float* __restrict__ gates) {
    int e = blockIdx.x * 256 + threadIdx.x;
    if (e >= HALL * MEAS) return;
    int row = e / MEAS, k = e % MEAS, n = row >> 7;
    float sc = 1.f;
    if (k < Dd) sc = 1.f / (1.f + expf(-gates[n * Dd + k]));
    split2(W1[e] * sc, g_W1h[e], g_W1l[e]);
}
__global__ void pre_M_Mu(const float* __restrict__ Wout, const float* __restrict__ Bmat) {
    int e = blockIdx.x * 256 + threadIdx.x;
    if (e < NBR * Dd * RH) {
        int n = e / (Dd * RH), rem = e % (Dd * RH), d = rem / RH, j = rem % RH;
        const float* wr = Wout + (n * Dd + d) * RH;
        const float* br = Bmat + n * RH * (RH + UD) + j;
        float s = 0.f;
        #pragma unroll 8
        for (int r = 0; r < RH; r++) s += wr[r] * br[r * (RH + UD)];
        g_M[e] = s;
    } else {
        int e2 = e - NBR * Dd * RH;
        if (e2 < Dd * UD) {
            int d = e2 / UD, u = e2 % UD;
            float s = 0.f;
            for (int n = 0; n < NBR; n++) {
                const float* wr = Wout + (n * Dd + d) * RH;
                const float* br = Bmat + n * RH * (RH + UD) + RH + u;
                #pragma unroll 8
                for (int r = 0; r < RH; r++) s += wr[r] * br[r * (RH + UD)];
            }
            g_Mu[e2] = s;
        }
    }
}
__global__ void pre_P(const float* __restrict__ W2, const float* __restrict__ b2) {
    int e = blockIdx.x * 256 + threadIdx.x;
    if (e < NBR * Dd * MH) {
        int n = e / (Dd * MH), rem = e % (Dd * MH), d = rem / MH, h = rem % MH;
        const float* m = g_M + (n * Dd + d) * RH;
        const float* w = W2 + n * RH * MH + h;
        float s = 0.f;
        #pragma unroll 8
        for (int j = 0; j < RH; j++) s += m[j] * w[j * MH];
        g_Pf[d * HALL + n * MH + h] = s;
    } else if (e < NBR * Dd * MH + Dd) {
        int d = e - NBR * Dd * MH;
        float s = 0.f;
        for (int n = 0; n < NBR; n++) {
            const float* m = g_M + (n * Dd + d) * RH;
            const float* bb = b2 + n * RH;
            #pragma unroll 8
            for (int j = 0; j < RH; j++) s += m[j] * bb[j];
        }
        g_zbias[d] = s;
    }
}
__global__ void pre_B2a() {
    int e = blockIdx.x * 256 + threadIdx.x;
    if (e >= Dd * K2) return;
    int n = e / K2, k = e % K2;
    float v = (k < HALL) ? g_Pf[n * HALL + k] : g_Mu[n * UD + (k - HALL)];
    split2(v, g_B2h[e], g_B2l[e]);
    if (k == 0) g_bias2[n] = g_zbias[n];
}
__global__ void pre_B2b(const float* __restrict__ C, const float* __restrict__ Dm) {
    __shared__ float sC[Dd];
    int o = blockIdx.x, tid = threadIdx.x, n = Dd + o;
    if (o >= NOBS) {
        for (int k = tid; k < K2; k += 256) {
            g_B2h[n * K2 + k] = __float2bfloat16(0.f);
            g_B2l[n * K2 + k] = __float2bfloat16(0.f);
        }
        if (tid == 0) g_bias2[n] = 0.f;
        return;
    }
    sC[tid] = C[o * Dd + tid];
    __syncthreads();
    for (int k = tid; k < K2; k += 256) {
        float s;
        if (k < HALL) {
            s = 0.f;
            #pragma unroll 8
            for (int d = 0; d < Dd; d++) s += sC[d] * g_Pf[d * HALL + k];
        } else {
            int u = k - HALL;
            s = Dm[o * UD + u];
            #pragma unroll 8
            for (int d = 0; d < Dd; d++) s += sC[d] * g_Mu[d * UD + u];
        }
        split2(s, g_B2h[n * K2 + k], g_B2l[n * K2 + k]);
    }
    if (tid == 0) {
        float s = 0.f;
        #pragma unroll 8
        for (int d = 0; d < Dd; d++) s += sC[d] * g_zbias[d];
        g_bias2[n] = s;
    }
}

// ======================= main kernel (512 threads) =======================
__global__ __launch_bounds__(512, 1) void skolr3(
    const float* __restrict__ z_dyn, const float* __restrict__ z_static,
    const float* __restrict__ dtp,   const float* __restrict__ ut,
    const float* __restrict__ b1g,   const float* __restrict__ gammag,
    const float* __restrict__ betag, float* __restrict__ out)
{
    extern __shared__ char sm[];
    const uint32_t smb = smem_u32(sm);
    const int tid = threadIdx.x, w = tid >> 5, lane = tid & 31;
    const int wm = w >> 2, wn = w & 3;          // 4M x 4N warp grid
    const int g = lane >> 2, t4 = lane & 3;
    const int row0 = blockIdx.x * TM;
    const float dt = dtp[0];

    const int sub = lane >> 3;
    const uint32_t aRow = ((uint32_t)(sub & 1)) * 8 + (lane & 7);
    const uint32_t aCh  = ((uint32_t)(sub >> 1)) * 16;
    const uint32_t bRow = ((uint32_t)(sub >> 1)) * 8 + (lane & 7);
    const uint32_t bCh  = ((uint32_t)(sub & 1)) * 16;

    float* lns = (float*)(sm + OFF_LN);         // [4][64]
    float* lnq = lns + 256;                     // [4][64]

    // ---- u*dt into H columns 512..527 (hi/lo planes) ----
    if (tid < 256) {
        int m = tid >> 2, q = tid & 3;
        float4 f = *(const float4*)&ut[(size_t)(row0 + m) * UD + q * 4];
        f.x *= dt; f.y *= dt; f.z *= dt; f.w *= dt;
        __nv_bfloat16 h0, l0, h1, l1, h2, l2, h3, l3;
        split2(f.x, h0, l0); split2(f.y, h1, l1); split2(f.z, h2, l2); split2(f.w, h3, l3);
        uint2 hp, lp;
        hp.x = (uint32_t)__bfloat16_as_ushort(h0) | ((uint32_t)__bfloat16_as_ushort(h1) << 16);
        hp.y = (uint32_t)__bfloat16_as_ushort(h2) | ((uint32_t)__bfloat16_as_ushort(h3) << 16);
        lp.x = (uint32_t)__bfloat16_as_ushort(l0) | ((uint32_t)__bfloat16_as_ushort(l1) << 16);
        lp.y = (uint32_t)__bfloat16_as_ushort(l2) | ((uint32_t)__bfloat16_as_ushort(l3) << 16);
        *(uint2*)(sm + m * HSTR + 1024 + q * 8)      = hp;
        *(uint2*)(sm + HP + m * HSTR + 1024 + q * 8) = lp;
    }

    // ================= GEMM1 (2 halves of 256 cols) + fused LN/GELU =================
    for (int p = 0; p < 2; p++) {
        float acc[8][4];
        #pragma unroll
        for (int i = 0; i < 8; i++) { acc[i][0] = acc[i][1] = acc[i][2] = acc[i][3] = 0.f; }

        #define STAGE1(kc_, buf_) do { \
            int _kc = (kc_), _bf = (buf_); \
            if (tid < 256) { int m = tid >> 2, q = tid & 3; \
              float4 f = (_kc < 16) \
                ? *(const float4*)&z_dyn[(size_t)(row0 + m) * Dd + _kc * 16 + q * 4] \
                : *(const float4*)&z_static[(size_t)(row0 + m) * SDIM + (_kc - 16) * 16 + q * 4]; \
              __nv_bfloat16 h0, l0, h1, l1, h2, l2, h3, l3; \
              split2(f.x, h0, l0); split2(f.y, h1, l1); split2(f.z, h2, l2); split2(f.w, h3, l3); \
              uint2 hp, lp; \
              hp.x = (uint32_t)__bfloat16_as_ushort(h0) | ((uint32_t)__bfloat16_as_ushort(h1) << 16); \
              hp.y = (uint32_t)__bfloat16_as_ushort(h2) | ((uint32_t)__bfloat16_as_ushort(h3) << 16); \
              lp.x = (uint32_t)__bfloat16_as_ushort(l0) | ((uint32_t)__bfloat16_as_ushort(l1) << 16); \
              lp.y = (uint32_t)__bfloat16_as_ushort(l2) | ((uint32_t)__bfloat16_as_ushort(l3) << 16); \
              char* ab = sm + OFF_AB + _bf * ABUF + m * 48 + q * 8; \
              *(uint2*)ab = hp; *(uint2*)(ab + APL) = lp; } \
            _Pragma("unroll") \
            for (int t = 0; t < 2; t++) { \
                int comp = tid + t * 512; \
                int n = comp & 255, h16 = (comp >> 8) & 1, pl = comp >> 9; \
                const __nv_bfloat16* src = (pl ? g_W1l : g_W1h) + (size_t)(p * 256 + n) * MEAS + _kc * 16 + h16 * 8; \
                uint32_t dst = smb + OFF_BB + _bf * BBUF + pl * BPL + n * 48 + h16 * 16; \
                CPA(dst, src); \
            } \
        } while (0)

        STAGE1(0, 0); CPC();
        for (int kc = 0; kc < 20; kc++) {
            if (kc < 19) { STAGE1(kc + 1, (kc + 1) & 1); CPC(); CPW1(); } else { CPW0(); }
            __syncthreads();
            const int buf = kc & 1;
            uint32_t ah[4], al[4];
            uint32_t aaddr = smb + OFF_AB + buf * ABUF + (wm * 16 + aRow) * 48 + aCh;
            LDSM4(ah, aaddr); LDSM4(al, aaddr + APL);
            uint32_t bbase = smb + OFF_BB + buf * BBUF + (wn * 64 + bRow) * 48 + bCh;
            #pragma unroll
            for (int q = 0; q < 4; q++) {
                uint32_t bh[4], bl[4];
                uint32_t ba = bbase + q * (16 * 48);
                LDSM4(bh, ba); LDSM4(bl, ba + BPL);
                mma_bf16(acc[q * 2],     ah, bh);     mma_bf16(acc[q * 2],     ah, bl);
                mma_bf16(acc[q * 2],     al, bh);
                mma_bf16(acc[q * 2 + 1], ah, bh + 2); mma_bf16(acc[q * 2 + 1], ah, bl + 2);
                mma_bf16(acc[q * 2 + 1], al, bh + 2);
            }
            __syncthreads();
        }
        #undef STAGE1

        // ---- epilogue: +b1, LN(128) via t4 shuffles + warp-pair smem reduce, GELU -> H ----
        float s0 = 0.f, q0 = 0.f, s1 = 0.f, q1 = 0.f;
        #pragma unroll
        for (int nt = 0; nt < 8; nt++) {
            int c = p * 256 + wn * 64 + nt * 8 + t4 * 2;
            float2 bv = __ldg((const float2*)&b1g[c]);
            acc[nt][0] += bv.x; acc[nt][1] += bv.y; acc[nt][2] += bv.x; acc[nt][3] += bv.y;
            s0 += acc[nt][0] + acc[nt][1];
            q0 = fmaf(acc[nt][0], acc[nt][0], fmaf(acc[nt][1], acc[nt][1], q0));
            s1 += acc[nt][2] + acc[nt][3];
            q1 = fmaf(acc[nt][2], acc[nt][2], fmaf(acc[nt][3], acc[nt][3], q1));
        }
        #pragma unroll
        for (int o = 1; o <= 2; o <<= 1) {
            s0 += __shfl_xor_sync(0xffffffffu, s0, o);
            q0 += __shfl_xor_sync(0xffffffffu, q0, o);
            s1 += __shfl_xor_sync(0xffffffffu, s1, o);
            q1 += __shfl_xor_sync(0xffffffffu, q1, o);
        }
        const int rA = wm * 16 + g, rB = rA + 8;
        if (t4 == 0) {
            lns[wn * 64 + rA] = s0; lnq[wn * 64 + rA] = q0;
            lns[wn * 64 + rB] = s1; lnq[wn * 64 + rB] = q1;
        }
        __syncthreads();
        const int pw = wn ^ 1;
        float s0t = s0 + lns[pw * 64 + rA], q0t = q0 + lnq[pw * 64 + rA];
        float s1t = s1 + lns[pw * 64 + rB], q1t = q1 + lnq[pw * 64 + rB];
        const float mean0 = s0t * (1.f / 128.f);
        const float inv0  = rsqrtf(q0t * (1.f / 128.f) - mean0 * mean0 + 1e-5f);
        const float mean1 = s1t * (1.f / 128.f);
        const float inv1  = rsqrtf(q1t * (1.f / 128.f) - mean1 * mean1 + 1e-5f);
        #pragma unroll
        for (int nt = 0; nt < 8; nt++) {
            int c = p * 256 + wn * 64 + nt * 8 + t4 * 2;
            float2 gv = __ldg((const float2*)&gammag[c]);
            float2 ev = __ldg((const float2*)&betag[c]);
            float t0 = (acc[nt][0] - mean0) * inv0 * gv.x + ev.x;
            float t1 = (acc[nt][1] - mean0) * inv0 * gv.y + ev.y;
            float t2 = (acc[nt][2] - mean1) * inv1 * gv.x + ev.x;
            float t3 = (acc[nt][3] - mean1) * inv1 * gv.y + ev.y;
            t0 = 0.5f * t0 * (1.f + erff(t0 * 0.70710678118654752f));
            t1 = 0.5f * t1 * (1.f + erff(t1 * 0.70710678118654752f));
            t2 = 0.5f * t2 * (1.f + erff(t2 * 0.70710678118654752f));
            t3 = 0.5f * t3 * (1.f + erff(t3 * 0.70710678118654752f));
            __nv_bfloat16 x0, y0, x1, y1, x2, y2, x3, y3;
            split2(t0, x0, y0); split2(t1, x1, y1); split2(t2, x2, y2); split2(t3, x3, y3);
            uint32_t hA = (uint32_t)__bfloat16_as_ushort(x0) | ((uint32_t)__bfloat16_as_ushort(x1) << 16);
            uint32_t lA = (uint32_t)__bfloat16_as_ushort(y0) | ((uint32_t)__bfloat16_as_ushort(y1) << 16);
            uint32_t hB = (uint32_t)__bfloat16_as_ushort(x2) | ((uint32_t)__bfloat16_as_ushort(x3) << 16);
            uint32_t lB = (uint32_t)__bfloat16_as_ushort(y2) | ((uint32_t)__bfloat16_as_ushort(y3) << 16);
            *(uint32_t*)(sm + rA * HSTR + c * 2)      = hA;
            *(uint32_t*)(sm + HP + rA * HSTR + c * 2) = lA;
            *(uint32_t*)(sm + rB * HSTR + c * 2)      = hB;
            *(uint32_t*)(sm + HP + rB * HSTR + c * 2) = lB;
        }
        __syncthreads();
    }

    // ================= GEMM2: [64][320] = H[64][528] x B2^T =================
    float acc2[10][4];
    #pragma unroll
    for (int i = 0; i < 10; i++) { acc2[i][0] = acc2[i][1] = acc2[i][2] = acc2[i][3] = 0.f; }

    #define STAGE2(kc_, buf_) do { \
        int _kc = (kc_), _bf = (buf_); \
        for (int idx = tid; idx < 1280; idx += 512) { \
            int n = idx >> 2, rem = idx & 3, h16 = rem & 1, pl = rem >> 1; \
            const __nv_bfloat16* src = (pl ? g_B2l : g_B2h) + (size_t)n * K2 + _kc * 16 + h16 * 8; \
            uint32_t dst = smb + OFF_BB + _bf * BBUF + pl * BPL + n * 48 + h16 * 16; \
            CPA(dst, src); \
        } \
    } while (0)

    STAGE2(0, 0); CPC();
    for (int kc = 0; kc < 33; kc++) {
        if (kc < 32) { STAGE2(kc + 1, (kc + 1) & 1); CPC(); CPW1(); } else { CPW0(); }
        __syncthreads();
        const int buf = kc & 1;
        uint32_t ah[4], al[4];
        uint32_t aaddr = smb + (wm * 16 + aRow) * HSTR + kc * 32 + aCh;
        LDSM4(ah, aaddr); LDSM4(al, aaddr + HP);
        uint32_t bbase = smb + OFF_BB + buf * BBUF + (wn * 80 + bRow) * 48 + bCh;
        #pragma unroll
        for (int q = 0; q < 5; q++) {
            uint32_t bh[4], bl[4];
            uint32_t ba = bbase + q * (16 * 48);
            LDSM4(bh, ba); LDSM4(bl, ba + BPL);
            mma_bf16(acc2[q * 2],     ah, bh);     mma_bf16(acc2[q * 2],     ah, bl);
            mma_bf16(acc2[q * 2],     al, bh);
            mma_bf16(acc2[q * 2 + 1], ah, bh + 2); mma_bf16(acc2[q * 2 + 1], ah, bl + 2);
            mma_bf16(acc2[q * 2 + 1], al, bh + 2);
        }
        __syncthreads();
    }
    #undef STAGE2

    // ---- epilogue: +bias2; write z_next and yt ----
    float* out_yt = out + (size_t)BSZ * Dd;
    #pragma unroll
    for (int nt = 0; nt < 10; nt++) {
        const int n0 = wn * 80 + nt * 8 + t4 * 2;
        float2 bv = __ldg((const float2*)&g_bias2[n0]);
        const int r = wm * 16 + g;
        float v0 = acc2[nt][0] + bv.x, v1 = acc2[nt][1] + bv.y;
        float v2 = acc2[nt][2] + bv.x, v3 = acc2[nt][3] + bv.y;
        if (n0 < Dd) {
            *(float2*)&out[(size_t)(row0 + r) * Dd + n0]     = make_float2(v0, v1);
            *(float2*)&out[(size_t)(row0 + r + 8) * Dd + n0] = make_float2(v2, v3);
        } else {
            const int o = n0 - Dd;
            if (o < NOBS)     { out_yt[(size_t)(row0 + r) * NOBS + o]     = v0;
                                out_yt[(size_t)(row0 + r + 8) * NOBS + o] = v2; }
            if (o + 1 < NOBS) { out_yt[(size_t)(row0 + r) * NOBS + o + 1]     = v1;
                                out_yt[(size_t)(row0 + r + 8) * NOBS + o + 1] = v3; }
        }
    }
}

extern "C" void kernel_launch(void* const* d_in, const int* in_sizes, int n_in,
                              void* d_out, int out_size) {
    const float* z_dyn    = (const float*)d_in[0];
    const float* z_static = (const float*)d_in[1];
    const float* dt       = (const float*)d_in[2];
    const float* ut       = (const float*)d_in[3];
    const float* gates    = (const float*)d_in[4];
    const float* W1       = (const float*)d_in[5];
    const float* b1       = (const float*)d_in[6];
    const float* gamma    = (const float*)d_in[7];
    const float* beta     = (const float*)d_in[8];
    const float* W2       = (const float*)d_in[9];
    const float* b2       = (const float*)d_in[10];
    const float* Bmat     = (const float*)d_in[13];
    const float* Wout     = (const float*)d_in[14];
    const float* Cmat     = (const float*)d_in[15];
    const float* Dm       = (const float*)d_in[16];
    float* out = (float*)d_out;

    pre_w1<<<(HALL * MEAS + 255) / 256, 256>>>(W1, gates);
    pre_M_Mu<<<(NBR * Dd * RH + Dd * UD + 255) / 256, 256>>>(Wout, Bmat);
    pre_P<<<(NBR * Dd * MH + Dd + 255) / 256, 256>>>(W2, b2);
    pre_B2a<<<(Dd * K2 + 255) / 256, 256>>>();
    pre_B2b<<<N2P - Dd, 256>>>(Cmat, Dm);

    cudaFuncSetAttribute(skolr3, cudaFuncAttributeMaxDynamicSharedMemorySize, SMEM_TOTAL);
    skolr3<<<BSZ / TM, 512, SMEM_TOTAL>>>(z_dyn, z_static, dt, ut, b1, gamma, beta, out);
}

// round 13
// speedup vs baseline: 1.2288x; 1.2288x over previous
#include <cuda_runtime.h>
#include <cuda_bf16.h>
#include <math.h>
#include <stdint.h>

#define NBR 4
#define Dd 256
#define SDIM 64
#define MEAS 320
#define MH 128
#define RH 64
#define UD 16
#define NOBS 25
#define BSZ 32768
#define HALL 512
#define K3 272             // stage-2 K: 256 G cols + 16 u cols
#define N2 288             // stage-2 outs: 256 z + 25 yt + pad
#define TM 64

__device__ __nv_bfloat16 g_W1h[HALL * MEAS];
__device__ __nv_bfloat16 g_W1l[HALL * MEAS];
__device__ __nv_bfloat16 g_W2h[Dd * MH];       // 256 rows (n*64+j) x 128 K
__device__ __nv_bfloat16 g_W2l[Dd * MH];
__device__ float g_M[NBR * Dd * RH];           // M = Wout @ Bg
__device__ float g_Mu[Dd * UD];
__device__ __nv_bfloat16 g_B3h[N2 * K3];
__device__ __nv_bfloat16 g_B3l[N2 * K3];

// ---- smem layout (bytes) ----
#define HSTR 1072
#define HP   68608                 // 64*1072  (hi plane size)
#define OFF_BB 137216              // B tiles: 2 bufs x 2 planes x <=288 rows x 48B
#define BBUF 30720
#define BPL  15360
#define OFF_AB 198656              // A tiles (GEMM1): 2 bufs x 2 planes x 64 x 48B
#define ABUF 6144
#define APL  3072
#define OFF_SU 210944              // u*dt floats [64][16]
#define SMEM_TOTAL 215040

#define CPA(dst, src) asm volatile("cp.async.cg.shared.global [%0], [%1], 16;" :: "r"(dst), "l"(src))
#define CPC()  asm volatile("cp.async.commit_group;")
#define CPW1() asm volatile("cp.async.wait_group 1;")
#define CPW0() asm volatile("cp.async.wait_group 0;")

#define LDSM4(r, a) \
    asm volatile("ldmatrix.sync.aligned.m8n8.x4.shared.b16 {%0,%1,%2,%3}, [%4];" \
        : "=r"((r)[0]), "=r"((r)[1]), "=r"((r)[2]), "=r"((r)[3]) : "r"(a))

__device__ __forceinline__ void mma_bf16(float* d, const uint32_t* a, const uint32_t* b) {
    asm volatile(
        "mma.sync.aligned.m16n8k16.row.col.f32.bf16.bf16.f32 "
        "{%0,%1,%2,%3},{%4,%5,%6,%7},{%8,%9},{%0,%1,%2,%3};\n"
        : "+f"(d[0]), "+f"(d[1]), "+f"(d[2]), "+f"(d[3])
        : "r"(a[0]), "r"(a[1]), "r"(a[2]), "r"(a[3]), "r"(b[0]), "r"(b[1]));
}
__device__ __forceinline__ void split2(float v, __nv_bfloat16& hi, __nv_bfloat16& lo) {
    hi = __float2bfloat16(v);
    lo = __float2bfloat16(v - __bfloat162float(hi));
}
__device__ __forceinline__ uint32_t smem_u32(const void* p) {
    uint32_t a;
    asm("{ .reg .u64 t; cvta.to.shared.u64 t, %1; cvt.u32.u64 %0, t; }" : "=r"(a) : "l"(p));
    return a;
}

// ======================= precompute (2 kernels) =======================
__global__ void preK1(const float* __restrict__ W1, const float* __restrict__ gates,
                      const float* __restrict__ W2, const float* __restrict__ Wout,
                      const float* __restrict__ Bmat) {
    int bid = blockIdx.x, tid = threadIdx.x;
    if (bid < 640) {                            // W1eff split planes (163840)
        int e = bid * 256 + tid;
        int row = e / MEAS, k = e % MEAS, n = row >> 7;
        float sc = 1.f;
        if (k < Dd) sc = 1.f / (1.f + expf(-gates[n * Dd + k]));
        split2(W1[e] * sc, g_W1h[e], g_W1l[e]);
    } else if (bid < 768) {                     // W2 split planes (32768, flat copy)
        int e = (bid - 640) * 256 + tid;
        split2(W2[e], g_W2h[e], g_W2l[e]);
    } else if (bid < 1024) {                    // M = Wout @ Bg (65536)
        int e = (bid - 768) * 256 + tid;
        int n = e >> 14, rem = e & 16383, d = rem >> 6, j = rem & 63;
        const float* wr = Wout + (n * Dd + d) * RH;
        const float* br = Bmat + n * RH * (RH + UD) + j;
        float s = 0.f;
        #pragma unroll 8
        for (int r = 0; r < RH; r++) s += wr[r] * br[r * (RH + UD)];
        g_M[e] = s;
    } else {                                    // Mu (4096)
        int e = (bid - 1024) * 256 + tid;
        int d = e >> 4, u = e & 15;
        float s = 0.f;
        for (int n = 0; n < NBR; n++) {
            const float* wr = Wout + (n * Dd + d) * RH;
            const float* br = Bmat + n * RH * (RH + UD) + RH + u;
            #pragma unroll 8
            for (int r = 0; r < RH; r++) s += wr[r] * br[r * (RH + UD)];
        }
        g_Mu[e] = s;
    }
}

__global__ void preK2(const float* __restrict__ C, const float* __restrict__ Dm) {
    int bid = blockIdx.x, tid = threadIdx.x;
    if (bid < 272) {                            // z rows: pure relayout of M / Mu
        int e = bid * 256 + tid;                // < 69632 = 256*272
        int d = e / K3, c = e % K3;
        float v = (c < 256) ? g_M[(c >> 6) * (Dd * RH) + d * RH + (c & 63)]
                            : g_Mu[d * UD + (c - 256)];
        split2(v, g_B3h[e], g_B3l[e]);
    } else if (bid < 272 + NOBS) {              // yt rows: CM = C @ M per block
        int o = bid - 272;
        __shared__ float sCM[256];
        int n = tid >> 6, j = tid & 63;
        const float* cr = C + o * Dd;
        const float* mp = g_M + n * (Dd * RH) + j;
        float s = 0.f;
        #pragma unroll 8
        for (int d = 0; d < Dd; d++) s += cr[d] * mp[d * RH];
        sCM[tid] = s;
        __syncthreads();
        for (int c = tid; c < K3; c += 256) {
            float v;
            if (c < 256) v = sCM[c];
            else {
                int u = c - 256;
                v = Dm[o * UD + u];
                #pragma unroll 8
                for (int d = 0; d < Dd; d++) v += cr[d] * g_Mu[d * UD + u];
            }
            split2(v, g_B3h[(256 + o) * K3 + c], g_B3l[(256 + o) * K3 + c]);
        }
    } else {                                    // pad rows 281..287 -> zero
        int e = (bid - 272 - NOBS) * 256 + tid;
        if (e < (N2 - 256 - NOBS) * K3) {
            int r = 256 + NOBS + e / K3, c = e % K3;
            g_B3h[r * K3 + c] = __float2bfloat16(0.f);
            g_B3l[r * K3 + c] = __float2bfloat16(0.f);
        }
    }
}

// ======================= main kernel =======================
__global__ __launch_bounds__(256, 1) void skolr4(
    const float* __restrict__ z_dyn, const float* __restrict__ z_static,
    const float* __restrict__ dtp,   const float* __restrict__ ut,
    const float* __restrict__ b1g,   const float* __restrict__ gammag,
    const float* __restrict__ betag, const float* __restrict__ b2g,
    float* __restrict__ out)
{
    extern __shared__ char sm[];
    const uint32_t smb = smem_u32(sm);
    const int tid = threadIdx.x, w = tid >> 5, lane = tid & 31;
    const int wm = w >> 1, wn = w & 1;
    const int g = lane >> 2, t4 = lane & 3;
    const int row0 = blockIdx.x * TM;
    const float dt = dtp[0];

    const int sub = lane >> 3;
    const uint32_t aRow = ((uint32_t)(sub & 1)) * 8 + (lane & 7);
    const uint32_t aCh  = ((uint32_t)(sub >> 1)) * 16;
    const uint32_t bRow = ((uint32_t)(sub >> 1)) * 8 + (lane & 7);
    const uint32_t bCh  = ((uint32_t)(sub & 1)) * 16;

    float* su = (float*)(sm + OFF_SU);

    // ---- u*dt into float scratch (consumed in stage-1 epilogue) ----
    {
        int m = tid >> 2, q = tid & 3;
        float4 f = *(const float4*)&ut[(size_t)(row0 + m) * UD + q * 4];
        f.x *= dt; f.y *= dt; f.z *= dt; f.w *= dt;
        *(float4*)&su[m * UD + q * 4] = f;
    }

    // ================= GEMM1 (2 halves of 256 cols) + fused LN/GELU =================
    for (int p = 0; p < 2; p++) {
        float acc[16][4];
        #pragma unroll
        for (int i = 0; i < 16; i++) { acc[i][0] = acc[i][1] = acc[i][2] = acc[i][3] = 0.f; }

        #define STAGE1(kc_, buf_) do { \
            int _kc = (kc_), _bf = (buf_); \
            { int m = tid >> 2, q = tid & 3; \
              float4 f = (_kc < 16) \
                ? *(const float4*)&z_dyn[(size_t)(row0 + m) * Dd + _kc * 16 + q * 4] \
                : *(const float4*)&z_static[(size_t)(row0 + m) * SDIM + (_kc - 16) * 16 + q * 4]; \
              __nv_bfloat16 h0, l0, h1, l1, h2, l2, h3, l3; \
              split2(f.x, h0, l0); split2(f.y, h1, l1); split2(f.z, h2, l2); split2(f.w, h3, l3); \
              uint2 hp, lp; \
              hp.x = (uint32_t)__bfloat16_as_ushort(h0) | ((uint32_t)__bfloat16_as_ushort(h1) << 16); \
              hp.y = (uint32_t)__bfloat16_as_ushort(h2) | ((uint32_t)__bfloat16_as_ushort(h3) << 16); \
              lp.x = (uint32_t)__bfloat16_as_ushort(l0) | ((uint32_t)__bfloat16_as_ushort(l1) << 16); \
              lp.y = (uint32_t)__bfloat16_as_ushort(l2) | ((uint32_t)__bfloat16_as_ushort(l3) << 16); \
              char* ab = sm + OFF_AB + _bf * ABUF + m * 48 + q * 8; \
              *(uint2*)ab = hp; *(uint2*)(ab + APL) = lp; } \
            _Pragma("unroll") \
            for (int t = 0; t < 4; t++) { \
                int comp = tid + t * 256; \
                int n = comp & 255, h16 = (comp >> 8) & 1, pl = comp >> 9; \
                const __nv_bfloat16* src = (pl ? g_W1l : g_W1h) + (size_t)(p * 256 + n) * MEAS + _kc * 16 + h16 * 8; \
                uint32_t dst = smb + OFF_BB + _bf * BBUF + pl * BPL + n * 48 + h16 * 16; \
                CPA(dst, src); \
            } \
        } while (0)

        STAGE1(0, 0); CPC();
        for (int kc = 0; kc < 20; kc++) {
            if (kc < 19) { STAGE1(kc + 1, (kc + 1) & 1); CPC(); CPW1(); } else { CPW0(); }
            __syncthreads();
            const int buf = kc & 1;
            uint32_t ah[4], al[4];
            uint32_t aaddr = smb + OFF_AB + buf * ABUF + (wm * 16 + aRow) * 48 + aCh;
            LDSM4(ah, aaddr); LDSM4(al, aaddr + APL);
            uint32_t bbase = smb + OFF_BB + buf * BBUF + (wn * 128 + bRow) * 48 + bCh;
            #pragma unroll
            for (int q = 0; q < 8; q++) {
                uint32_t bh[4], bl[4];
                uint32_t ba = bbase + q * (16 * 48);
                LDSM4(bh, ba); LDSM4(bl, ba + BPL);
                mma_bf16(acc[q * 2],     ah, bh);     mma_bf16(acc[q * 2],     ah, bl);
                mma_bf16(acc[q * 2],     al, bh);
                mma_bf16(acc[q * 2 + 1], ah, bh + 2); mma_bf16(acc[q * 2 + 1], ah, bl + 2);
                mma_bf16(acc[q * 2 + 1], al, bh + 2);
            }
            __syncthreads();
        }
        #undef STAGE1

        // ---- epilogue: +b1, LN(128), GELU, split -> H ----
        float s0 = 0.f, q0 = 0.f, s1 = 0.f, q1 = 0.f;
        #pragma unroll
        for (int nt = 0; nt < 16; nt++) {
            int c = p * 256 + wn * 128 + nt * 8 + t4 * 2;
            float2 bv = __ldg((const float2*)&b1g[c]);
            acc[nt][0] += bv.x; acc[nt][1] += bv.y; acc[nt][2] += bv.x; acc[nt][3] += bv.y;
            s0 += acc[nt][0] + acc[nt][1];
            q0 = fmaf(acc[nt][0], acc[nt][0], fmaf(acc[nt][1], acc[nt][1], q0));
            s1 += acc[nt][2] + acc[nt][3];
            q1 = fmaf(acc[nt][2], acc[nt][2], fmaf(acc[nt][3], acc[nt][3], q1));
        }
        #pragma unroll
        for (int o = 1; o <= 2; o <<= 1) {
            s0 += __shfl_xor_sync(0xffffffffu, s0, o);
            q0 += __shfl_xor_sync(0xffffffffu, q0, o);
            s1 += __shfl_xor_sync(0xffffffffu, s1, o);
            q1 += __shfl_xor_sync(0xffffffffu, q1, o);
        }
        const float mean0 = s0 * (1.f / 128.f);
        const float inv0  = rsqrtf(q0 * (1.f / 128.f) - mean0 * mean0 + 1e-5f);
        const float mean1 = s1 * (1.f / 128.f);
        const float inv1  = rsqrtf(q1 * (1.f / 128.f) - mean1 * mean1 + 1e-5f);
        const int rA = wm * 16 + g, rB = rA + 8;
        #pragma unroll
        for (int nt = 0; nt < 16; nt++) {
            int c = p * 256 + wn * 128 + nt * 8 + t4 * 2;
            float2 gv = __ldg((const float2*)&gammag[c]);
            float2 ev = __ldg((const float2*)&betag[c]);
            float t0 = (acc[nt][0] - mean0) * inv0 * gv.x + ev.x;
            float t1 = (acc[nt][1] - mean0) * inv0 * gv.y + ev.y;
            float t2 = (acc[nt][2] - mean1) * inv1 * gv.x + ev.x;
            float t3 = (acc[nt][3] - mean1) * inv1 * gv.y + ev.y;
            t0 = 0.5f * t0 * (1.f + erff(t0 * 0.70710678118654752f));
            t1 = 0.5f * t1 * (1.f + erff(t1 * 0.70710678118654752f));
            t2 = 0.5f * t2 * (1.f + erff(t2 * 0.70710678118654752f));
            t3 = 0.5f * t3 * (1.f + erff(t3 * 0.70710678118654752f));
            __nv_bfloat16 x0, y0, x1, y1, x2, y2, x3, y3;
            split2(t0, x0, y0); split2(t1, x1, y1); split2(t2, x2, y2); split2(t3, x3, y3);
            uint32_t hA = (uint32_t)__bfloat16_as_ushort(x0) | ((uint32_t)__bfloat16_as_ushort(x1) << 16);
            uint32_t lA = (uint32_t)__bfloat16_as_ushort(y0) | ((uint32_t)__bfloat16_as_ushort(y1) << 16);
            uint32_t hB = (uint32_t)__bfloat16_as_ushort(x2) | ((uint32_t)__bfloat16_as_ushort(x3) << 16);
            uint32_t lB = (uint32_t)__bfloat16_as_ushort(y2) | ((uint32_t)__bfloat16_as_ushort(y3) << 16);
            *(uint32_t*)(sm + rA * HSTR + c * 2)      = hA;
            *(uint32_t*)(sm + HP + rA * HSTR + c * 2) = lA;
            *(uint32_t*)(sm + rB * HSTR + c * 2)      = hB;
            *(uint32_t*)(sm + HP + rB * HSTR + c * 2) = lB;
        }
    }

    // ================= GEMM2 stage-1: G[n] = H[n] @ W2[n]^T + b2 (block-diagonal) =================
    float acc1[16][4];
    #pragma unroll
    for (int i = 0; i < 16; i++) { acc1[i][0] = acc1[i][1] = acc1[i][2] = acc1[i][3] = 0.f; }

    #define STAGEW2(kc_, buf_) do { \
        int _kc = (kc_), _bf = (buf_); \
        _Pragma("unroll") \
        for (int t = 0; t < 4; t++) { \
            int comp = tid + t * 256; \
            int n = comp & 255, h16 = (comp >> 8) & 1, pl = comp >> 9; \
            const __nv_bfloat16* src = (pl ? g_W2l : g_W2h) + (size_t)n * MH + _kc * 16 + h16 * 8; \
            uint32_t dst = smb + OFF_BB + _bf * BBUF + pl * BPL + n * 48 + h16 * 16; \
            CPA(dst, src); \
        } \
    } while (0)

    STAGEW2(0, 0); CPC();
    for (int i = 0; i < 16; i++) {
        if (i < 15) { STAGEW2((i + 1) & 7, (i + 1) & 1); CPC(); CPW1(); } else { CPW0(); }
        __syncthreads();
        const int buf = i & 1;
        const int bn = 2 * wn + (i >> 3);
        const int kc = i & 7;
        const int ab = (i >> 3) * 8;
        uint32_t ah[4], al[4];
        uint32_t aaddr = smb + (wm * 16 + aRow) * HSTR + bn * 256 + kc * 32 + aCh;
        LDSM4(ah, aaddr); LDSM4(al, aaddr + HP);
        uint32_t bbase = smb + OFF_BB + buf * BBUF + (bn * 64 + bRow) * 48 + bCh;
        #pragma unroll
        for (int q = 0; q < 4; q++) {
            uint32_t bh[4], bl[4];
            uint32_t ba = bbase + q * (16 * 48);
            LDSM4(bh, ba); LDSM4(bl, ba + BPL);
            mma_bf16(acc1[ab + q * 2],     ah, bh);     mma_bf16(acc1[ab + q * 2],     ah, bl);
            mma_bf16(acc1[ab + q * 2],     al, bh);
            mma_bf16(acc1[ab + q * 2 + 1], ah, bh + 2); mma_bf16(acc1[ab + q * 2 + 1], ah, bl + 2);
            mma_bf16(acc1[ab + q * 2 + 1], al, bh + 2);
        }
        __syncthreads();
    }
    #undef STAGEW2

    // ---- stage-1 epilogue: +b2, split G -> H2 (overlays H bytes [0,512)); u -> cols 256..271 ----
    {
        const int rA = wm * 16 + g, rB = rA + 8;
        #pragma unroll
        for (int b = 0; b < 2; b++) {
            #pragma unroll
            for (int nt = 0; nt < 8; nt++) {
                int c = (2 * wn + b) * 64 + nt * 8 + t4 * 2;
                float2 bv = __ldg((const float2*)&b2g[c]);
                float v0 = acc1[b * 8 + nt][0] + bv.x, v1 = acc1[b * 8 + nt][1] + bv.y;
                float v2 = acc1[b * 8 + nt][2] + bv.x, v3 = acc1[b * 8 + nt][3] + bv.y;
                __nv_bfloat16 x0, y0, x1, y1, x2, y2, x3, y3;
                split2(v0, x0, y0); split2(v1, x1, y1); split2(v2, x2, y2); split2(v3, x3, y3);
                uint32_t hA = (uint32_t)__bfloat16_as_ushort(x0) | ((uint32_t)__bfloat16_as_ushort(x1) << 16);
                uint32_t lA = (uint32_t)__bfloat16_as_ushort(y0) | ((uint32_t)__bfloat16_as_ushort(y1) << 16);
                uint32_t hB = (uint32_t)__bfloat16_as_ushort(x2) | ((uint32_t)__bfloat16_as_ushort(x3) << 16);
                uint32_t lB = (uint32_t)__bfloat16_as_ushort(y2) | ((uint32_t)__bfloat16_as_ushort(y3) << 16);
                *(uint32_t*)(sm + rA * HSTR + c * 2)      = hA;
                *(uint32_t*)(sm + HP + rA * HSTR + c * 2) = lA;
                *(uint32_t*)(sm + rB * HSTR + c * 2)      = hB;
                *(uint32_t*)(sm + HP + rB * HSTR + c * 2) = lB;
            }
        }
        for (int idx = tid; idx < TM * UD; idx += 256) {
            int m = idx >> 4, cu = idx & 15;
            __nv_bfloat16 hi, lo; split2(su[m * UD + cu], hi, lo);
            *(__nv_bfloat16*)(sm + m * HSTR + 512 + cu * 2)      = hi;
            *(__nv_bfloat16*)(sm + HP + m * HSTR + 512 + cu * 2) = lo;
        }
    }
    __syncthreads();

    // ================= GEMM2 stage-2: [z|yt][64][288] = [G|u][64][272] x B3^T =================
    float acc2[18][4];
    #pragma unroll
    for (int i = 0; i < 18; i++) { acc2[i][0] = acc2[i][1] = acc2[i][2] = acc2[i][3] = 0.f; }

    #define STAGE3(kc_, buf_) do { \
        int _kc = (kc_), _bf = (buf_); \
        for (int idx = tid; idx < 1152; idx += 256) { \
            int pl = idx / 576, rem = idx % 576, n = rem >> 1, h16 = rem & 1; \
            const __nv_bfloat16* src = (pl ? g_B3l : g_B3h) + (size_t)n * K3 + _kc * 16 + h16 * 8; \
            uint32_t dst = smb + OFF_BB + _bf * BBUF + pl * BPL + n * 48 + h16 * 16; \
            CPA(dst, src); \
        } \
    } while (0)

    STAGE3(0, 0); CPC();
    for (int kc = 0; kc < 17; kc++) {
        if (kc < 16) { STAGE3(kc + 1, (kc + 1) & 1); CPC(); CPW1(); } else { CPW0(); }
        __syncthreads();
        const int buf = kc & 1;
        uint32_t ah[4], al[4];
        uint32_t aaddr = smb + (wm * 16 + aRow) * HSTR + kc * 32 + aCh;
        LDSM4(ah, aaddr); LDSM4(al, aaddr + HP);
        uint32_t bbase = smb + OFF_BB + buf * BBUF + (wn * 144 + bRow) * 48 + bCh;
        #pragma unroll
        for (int q = 0; q < 9; q++) {
            uint32_t bh[4], bl[4];
            uint32_t ba = bbase + q * (16 * 48);
            LDSM4(bh, ba); LDSM4(bl, ba + BPL);
            mma_bf16(acc2[q * 2],     ah, bh);     mma_bf16(acc2[q * 2],     ah, bl);
            mma_bf16(acc2[q * 2],     al, bh);
            mma_bf16(acc2[q * 2 + 1], ah, bh + 2); mma_bf16(acc2[q * 2 + 1], ah, bl + 2);
            mma_bf16(acc2[q * 2 + 1], al, bh + 2);
        }
        __syncthreads();
    }
    #undef STAGE3

    // ---- epilogue: write z_next and yt (bias fully folded; none needed) ----
    float* out_yt = out + (size_t)BSZ * Dd;
    #pragma unroll
    for (int nt = 0; nt < 18; nt++) {
        const int n0 = wn * 144 + nt * 8 + t4 * 2;
        const int r = wm * 16 + g;
        float v0 = acc2[nt][0], v1 = acc2[nt][1];
        float v2 = acc2[nt][2], v3 = acc2[nt][3];
        if (n0 < Dd) {
            *(float2*)&out[(size_t)(row0 + r) * Dd + n0]     = make_float2(v0, v1);
            *(float2*)&out[(size_t)(row0 + r + 8) * Dd + n0] = make_float2(v2, v3);
        } else {
            const int o = n0 - Dd;
            if (o < NOBS)     { out_yt[(size_t)(row0 + r) * NOBS + o]     = v0;
                                out_yt[(size_t)(row0 + r + 8) * NOBS + o] = v2; }
            if (o + 1 < NOBS) { out_yt[(size_t)(row0 + r) * NOBS + o + 1]     = v1;
                                out_yt[(size_t)(row0 + r + 8) * NOBS + o + 1] = v3; }
        }
    }
}

extern "C" void kernel_launch(void* const* d_in, const int* in_sizes, int n_in,
                              void* d_out, int out_size) {
    const float* z_dyn    = (const float*)d_in[0];
    const float* z_static = (const float*)d_in[1];
    const float* dt       = (const float*)d_in[2];
    const float* ut       = (const float*)d_in[3];
    const float* gates    = (const float*)d_in[4];
    const float* W1       = (const float*)d_in[5];
    const float* b1       = (const float*)d_in[6];
    const float* gamma    = (const float*)d_in[7];
    const float* beta     = (const float*)d_in[8];
    const float* W2       = (const float*)d_in[9];
    const float* b2       = (const float*)d_in[10];
    const float* Bmat     = (const float*)d_in[13];
    const float* Wout     = (const float*)d_in[14];
    const float* Cmat     = (const float*)d_in[15];
    const float* Dm       = (const float*)d_in[16];
    float* out = (float*)d_out;

    preK1<<<1040, 256>>>(W1, gates, W2, Wout, Bmat);
    preK2<<<272 + NOBS + 8, 256>>>(Cmat, Dm);

    cudaFuncSetAttribute(skolr4, cudaFuncAttributeMaxDynamicSharedMemorySize, SMEM_TOTAL);
    skolr4<<<BSZ / TM, 256, SMEM_TOTAL>>>(z_dyn, z_static, dt, ut, b1, gamma, beta, b2, out);
}

// round 14
// speedup vs baseline: 1.2690x; 1.0328x over previous
#include <cuda_runtime.h>
#include <cuda_fp16.h>
#include <math.h>
#include <stdint.h>

#define NBR 4
#define Dd 256
#define SDIM 64
#define MEAS 320
#define MH 128
#define RH 64
#define UD 16
#define NOBS 25
#define BSZ 32768
#define HALL 512
#define K3 272             // stage-2 K: 256 G cols + 16 u cols
#define N2 288             // stage-2 outs: 256 z + 25 yt + pad
#define TM 64

__device__ __half g_W1h[HALL * MEAS];
__device__ __half g_W1l[HALL * MEAS];
__device__ __half g_W2h[Dd * MH];
__device__ __half g_W2l[Dd * MH];
__device__ __half g_B3h[N2 * K3];
__device__ __half g_B3l[N2 * K3];

// ---- smem layout (bytes) ----
#define HSTR 1072
#define HP   68608                 // 64*1072  (hi plane size)
#define OFF_BB 137216
#define BBUF 30720
#define BPL  15360
#define OFF_AB 198656
#define ABUF 6144
#define APL  3072
#define OFF_SU 210944
#define SMEM_TOTAL 215040

#define CPA(dst, src) asm volatile("cp.async.cg.shared.global [%0], [%1], 16;" :: "r"(dst), "l"(src))
#define CPC()  asm volatile("cp.async.commit_group;")
#define CPW1() asm volatile("cp.async.wait_group 1;")
#define CPW0() asm volatile("cp.async.wait_group 0;")

#define LDSM4(r, a) \
    asm volatile("ldmatrix.sync.aligned.m8n8.x4.shared.b16 {%0,%1,%2,%3}, [%4];" \
        : "=r"((r)[0]), "=r"((r)[1]), "=r"((r)[2]), "=r"((r)[3]) : "r"(a))

__device__ __forceinline__ void mma_f32(float* d, const uint32_t* a, const uint32_t* b) {
    asm volatile(
        "mma.sync.aligned.m16n8k16.row.col.f32.f16.f16.f32 "
        "{%0,%1,%2,%3},{%4,%5,%6,%7},{%8,%9},{%0,%1,%2,%3};\n"
        : "+f"(d[0]), "+f"(d[1]), "+f"(d[2]), "+f"(d[3])
        : "r"(a[0]), "r"(a[1]), "r"(a[2]), "r"(a[3]), "r"(b[0]), "r"(b[1]));
}
__device__ __forceinline__ void mma_f16(uint32_t* d, const uint32_t* a, const uint32_t* b) {
    asm volatile(
        "mma.sync.aligned.m16n8k16.row.col.f16.f16.f16.f16 "
        "{%0,%1},{%2,%3,%4,%5},{%6,%7},{%0,%1};\n"
        : "+r"(d[0]), "+r"(d[1])
        : "r"(a[0]), "r"(a[1]), "r"(a[2]), "r"(a[3]), "r"(b[0]), "r"(b[1]));
}
__device__ __forceinline__ void addcorr(float* a, const uint32_t* c) {
    float2 x = __half22float2(*(const half2*)&c[0]);
    float2 y = __half22float2(*(const half2*)&c[1]);
    a[0] += x.x; a[1] += x.y; a[2] += y.x; a[3] += y.y;
}
__device__ __forceinline__ void splith(float v, __half& hi, __half& lo) {
    hi = __float2half_rn(v);
    lo = __float2half_rn(v - __half2float(hi));
}
__device__ __forceinline__ uint32_t packh(__half a, __half b) {
    return (uint32_t)__half_as_ushort(a) | ((uint32_t)__half_as_ushort(b) << 16);
}
__device__ __forceinline__ uint32_t smem_u32(const void* p) {
    uint32_t a;
    asm("{ .reg .u64 t; cvta.to.shared.u64 t, %1; cvt.u32.u64 %0, t; }" : "=r"(a) : "l"(p));
    return a;
}

// ======================= precompute: ONE kernel =======================
__global__ void preK(const float* __restrict__ W1, const float* __restrict__ gates,
                     const float* __restrict__ W2, const float* __restrict__ Wout,
                     const float* __restrict__ Bmat, const float* __restrict__ C,
                     const float* __restrict__ Dm) {
    int bid = blockIdx.x, tid = threadIdx.x;
    if (bid < 640) {                            // W1eff split planes
        int e = bid * 256 + tid;
        int row = e / MEAS, k = e % MEAS, n = row >> 7;
        float sc = 1.f;
        if (k < Dd) sc = 1.f / (1.f + expf(-gates[n * Dd + k]));
        splith(W1[e] * sc, g_W1h[e], g_W1l[e]);
    } else if (bid < 768) {                     // W2 split planes
        int e = (bid - 640) * 256 + tid;
        splith(W2[e], g_W2h[e], g_W2l[e]);
    } else if (bid < 1040) {                    // B3 z-rows: direct from Wout x Bmat
        int e = (bid - 768) * 256 + tid;        // e = d*K3 + c, d < 256
        int d = e / K3, c = e % K3;
        float s = 0.f;
        if (c < 256) {
            int n = c >> 6, j = c & 63;
            const float* wr = Wout + (n * Dd + d) * RH;
            const float* br = Bmat + n * RH * (RH + UD) + j;
            #pragma unroll 8
            for (int r = 0; r < RH; r++) s += wr[r] * br[r * (RH + UD)];
        } else {
            int u = c - 256;
            for (int n = 0; n < NBR; n++) {
                const float* wr = Wout + (n * Dd + d) * RH;
                const float* br = Bmat + n * RH * (RH + UD) + RH + u;
                #pragma unroll 8
                for (int r = 0; r < RH; r++) s += wr[r] * br[r * (RH + UD)];
            }
        }
        splith(s, g_B3h[e], g_B3l[e]);
    } else if (bid < 1040 + NOBS) {             // yt rows via CW = C @ Wout
        int o = bid - 1040;
        __shared__ float sCW[256];              // [n][r]
        {
            int n = tid >> 6, r = tid & 63;
            const float* cr = C + o * Dd;
            const float* wp = Wout + n * Dd * RH + r;
            float s = 0.f;
            #pragma unroll 8
            for (int d = 0; d < Dd; d++) s += cr[d] * wp[d * RH];
            sCW[tid] = s;
        }
        __syncthreads();
        for (int c = tid; c < K3; c += 256) {
            float v;
            if (c < 256) {
                int n = c >> 6, j = c & 63;
                const float* br = Bmat + n * RH * (RH + UD) + j;
                v = 0.f;
                #pragma unroll 8
                for (int r = 0; r < RH; r++) v += sCW[n * 64 + r] * br[r * (RH + UD)];
            } else {
                int u = c - 256;
                v = Dm[o * UD + u];
                for (int n = 0; n < NBR; n++) {
                    const float* br = Bmat + n * RH * (RH + UD) + RH + u;
                    #pragma unroll 8
                    for (int r = 0; r < RH; r++) v += sCW[n * 64 + r] * br[r * (RH + UD)];
                }
            }
            splith(v, g_B3h[(256 + o) * K3 + c], g_B3l[(256 + o) * K3 + c]);
        }
    } else {                                    // pad rows 281..287 -> zero
        int e = (bid - 1040 - NOBS) * 256 + tid;
        if (e < (N2 - 256 - NOBS) * K3) {
            int r = 256 + NOBS + e / K3, c = e % K3;
            g_B3h[r * K3 + c] = __float2half(0.f);
            g_B3l[r * K3 + c] = __float2half(0.f);
        }
    }
}

// ======================= main kernel =======================
__global__ __launch_bounds__(256, 1) void skolr5(
    const float* __restrict__ z_dyn, const float* __restrict__ z_static,
    const float* __restrict__ dtp,   const float* __restrict__ ut,
    const float* __restrict__ b1g,   const float* __restrict__ gammag,
    const float* __restrict__ betag, const float* __restrict__ b2g,
    float* __restrict__ out)
{
    extern __shared__ char sm[];
    const uint32_t smb = smem_u32(sm);
    const int tid = threadIdx.x, w = tid >> 5, lane = tid & 31;
    const int wm = w >> 1, wn = w & 1;
    const int g = lane >> 2, t4 = lane & 3;
    const int row0 = blockIdx.x * TM;
    const float dt = dtp[0];

    const int sub = lane >> 3;
    const uint32_t aRow = ((uint32_t)(sub & 1)) * 8 + (lane & 7);
    const uint32_t aCh  = ((uint32_t)(sub >> 1)) * 16;
    const uint32_t bRow = ((uint32_t)(sub >> 1)) * 8 + (lane & 7);
    const uint32_t bCh  = ((uint32_t)(sub & 1)) * 16;

    float* su = (float*)(sm + OFF_SU);

    {
        int m = tid >> 2, q = tid & 3;
        float4 f = *(const float4*)&ut[(size_t)(row0 + m) * UD + q * 4];
        f.x *= dt; f.y *= dt; f.z *= dt; f.w *= dt;
        *(float4*)&su[m * UD + q * 4] = f;
    }

    // ================= GEMM1 (2 halves of 256 cols) + fused LN/GELU =================
    for (int p = 0; p < 2; p++) {
        float acc[16][4];
        uint32_t corr[16][2];
        #pragma unroll
        for (int i = 0; i < 16; i++) {
            acc[i][0] = acc[i][1] = acc[i][2] = acc[i][3] = 0.f;
            corr[i][0] = corr[i][1] = 0u;
        }

        #define STAGE1(kc_, buf_) do { \
            int _kc = (kc_), _bf = (buf_); \
            { int m = tid >> 2, q = tid & 3; \
              float4 f = (_kc < 16) \
                ? *(const float4*)&z_dyn[(size_t)(row0 + m) * Dd + _kc * 16 + q * 4] \
                : *(const float4*)&z_static[(size_t)(row0 + m) * SDIM + (_kc - 16) * 16 + q * 4]; \
              __half h0, l0, h1, l1, h2, l2, h3, l3; \
              splith(f.x, h0, l0); splith(f.y, h1, l1); splith(f.z, h2, l2); splith(f.w, h3, l3); \
              uint2 hp, lp; \
              hp.x = packh(h0, h1); hp.y = packh(h2, h3); \
              lp.x = packh(l0, l1); lp.y = packh(l2, l3); \
              char* ab = sm + OFF_AB + _bf * ABUF + m * 48 + q * 8; \
              *(uint2*)ab = hp; *(uint2*)(ab + APL) = lp; } \
            _Pragma("unroll") \
            for (int t = 0; t < 4; t++) { \
                int comp = tid + t * 256; \
                int n = comp & 255, h16 = (comp >> 8) & 1, pl = comp >> 9; \
                const __half* src = (pl ? g_W1l : g_W1h) + (size_t)(p * 256 + n) * MEAS + _kc * 16 + h16 * 8; \
                uint32_t dst = smb + OFF_BB + _bf * BBUF + pl * BPL + n * 48 + h16 * 16; \
                CPA(dst, src); \
            } \
        } while (0)

        STAGE1(0, 0); CPC();
        for (int kc = 0; kc < 20; kc++) {
            if (kc < 19) { STAGE1(kc + 1, (kc + 1) & 1); CPC(); CPW1(); } else { CPW0(); }
            __syncthreads();
            const int buf = kc & 1;
            uint32_t ah[4], al[4];
            uint32_t aaddr = smb + OFF_AB + buf * ABUF + (wm * 16 + aRow) * 48 + aCh;
            LDSM4(ah, aaddr); LDSM4(al, aaddr + APL);
            uint32_t bbase = smb + OFF_BB + buf * BBUF + (wn * 128 + bRow) * 48 + bCh;
            #pragma unroll
            for (int q = 0; q < 8; q++) {
                uint32_t bh[4], bl[4];
                uint32_t ba = bbase + q * (16 * 48);
                LDSM4(bh, ba); LDSM4(bl, ba + BPL);
                mma_f32(acc[q * 2],      ah, bh);
                mma_f16(corr[q * 2],     ah, bl);
                mma_f16(corr[q * 2],     al, bh);
                mma_f32(acc[q * 2 + 1],  ah, bh + 2);
                mma_f16(corr[q * 2 + 1], ah, bl + 2);
                mma_f16(corr[q * 2 + 1], al, bh + 2);
            }
            __syncthreads();
        }
        #undef STAGE1

        // ---- epilogue: +corr, +b1, LN(128), GELU, split -> H ----
        float s0 = 0.f, q0 = 0.f, s1 = 0.f, q1 = 0.f;
        #pragma unroll
        for (int nt = 0; nt < 16; nt++) {
            addcorr(acc[nt], corr[nt]);
            int c = p * 256 + wn * 128 + nt * 8 + t4 * 2;
            float2 bv = __ldg((const float2*)&b1g[c]);
            acc[nt][0] += bv.x; acc[nt][1] += bv.y; acc[nt][2] += bv.x; acc[nt][3] += bv.y;
            s0 += acc[nt][0] + acc[nt][1];
            q0 = fmaf(acc[nt][0], acc[nt][0], fmaf(acc[nt][1], acc[nt][1], q0));
            s1 += acc[nt][2] + acc[nt][3];
            q1 = fmaf(acc[nt][2], acc[nt][2], fmaf(acc[nt][3], acc[nt][3], q1));
        }
        #pragma unroll
        for (int o = 1; o <= 2; o <<= 1) {
            s0 += __shfl_xor_sync(0xffffffffu, s0, o);
            q0 += __shfl_xor_sync(0xffffffffu, q0, o);
            s1 += __shfl_xor_sync(0xffffffffu, s1, o);
            q1 += __shfl_xor_sync(0xffffffffu, q1, o);
        }
        const float mean0 = s0 * (1.f / 128.f);
        const float inv0  = rsqrtf(q0 * (1.f / 128.f) - mean0 * mean0 + 1e-5f);
        const float mean1 = s1 * (1.f / 128.f);
        const float inv1  = rsqrtf(q1 * (1.f / 128.f) - mean1 * mean1 + 1e-5f);
        const int rA = wm * 16 + g, rB = rA + 8;
        #pragma unroll
        for (int nt = 0; nt < 16; nt++) {
            int c = p * 256 + wn * 128 + nt * 8 + t4 * 2;
            float2 gv = __ldg((const float2*)&gammag[c]);
            float2 ev = __ldg((const float2*)&betag[c]);
            float t0 = (acc[nt][0] - mean0) * inv0 * gv.x + ev.x;
            float t1 = (acc[nt][1] - mean0) * inv0 * gv.y + ev.y;
            float t2 = (acc[nt][2] - mean1) * inv1 * gv.x + ev.x;
            float t3 = (acc[nt][3] - mean1) * inv1 * gv.y + ev.y;
            t0 = 0.5f * t0 * (1.f + erff(t0 * 0.70710678118654752f));
            t1 = 0.5f * t1 * (1.f + erff(t1 * 0.70710678118654752f));
            t2 = 0.5f * t2 * (1.f + erff(t2 * 0.70710678118654752f));
            t3 = 0.5f * t3 * (1.f + erff(t3 * 0.70710678118654752f));
            __half x0, y0, x1, y1, x2, y2, x3, y3;
            splith(t0, x0, y0); splith(t1, x1, y1); splith(t2, x2, y2); splith(t3, x3, y3);
            *(uint32_t*)(sm + rA * HSTR + c * 2)      = packh(x0, x1);
            *(uint32_t*)(sm + HP + rA * HSTR + c * 2) = packh(y0, y1);
            *(uint32_t*)(sm + rB * HSTR + c * 2)      = packh(x2, x3);
            *(uint32_t*)(sm + HP + rB * HSTR + c * 2) = packh(y2, y3);
        }
    }

    // ================= stage-1: G[n] = H[n] @ W2[n]^T + b2 (block-diagonal) =================
    float acc1[16][4];
    uint32_t corr1[16][2];
    #pragma unroll
    for (int i = 0; i < 16; i++) {
        acc1[i][0] = acc1[i][1] = acc1[i][2] = acc1[i][3] = 0.f;
        corr1[i][0] = corr1[i][1] = 0u;
    }

    #define STAGEW2(kc_, buf_) do { \
        int _kc = (kc_), _bf = (buf_); \
        _Pragma("unroll") \
        for (int t = 0; t < 4; t++) { \
            int comp = tid + t * 256; \
            int n = comp & 255, h16 = (comp >> 8) & 1, pl = comp >> 9; \
            const __half* src = (pl ? g_W2l : g_W2h) + (size_t)n * MH + _kc * 16 + h16 * 8; \
            uint32_t dst = smb + OFF_BB + _bf * BBUF + pl * BPL + n * 48 + h16 * 16; \
            CPA(dst, src); \
        } \
    } while (0)

    STAGEW2(0, 0); CPC();
    for (int i = 0; i < 16; i++) {
        if (i < 15) { STAGEW2((i + 1) & 7, (i + 1) & 1); CPC(); CPW1(); } else { CPW0(); }
        __syncthreads();
        const int buf = i & 1;
        const int bn = 2 * wn + (i >> 3);
        const int kc = i & 7;
        const int ab = (i >> 3) * 8;
        uint32_t ah[4], al[4];
        uint32_t aaddr = smb + (wm * 16 + aRow) * HSTR + bn * 256 + kc * 32 + aCh;
        LDSM4(ah, aaddr); LDSM4(al, aaddr + HP);
        uint32_t bbase = smb + OFF_BB + buf * BBUF + (bn * 64 + bRow) * 48 + bCh;
        #pragma unroll
        for (int q = 0; q < 4; q++) {
            uint32_t bh[4], bl[4];
            uint32_t ba = bbase + q * (16 * 48);
            LDSM4(bh, ba); LDSM4(bl, ba + BPL);
            mma_f32(acc1[ab + q * 2],      ah, bh);
            mma_f16(corr1[ab + q * 2],     ah, bl);
            mma_f16(corr1[ab + q * 2],     al, bh);
            mma_f32(acc1[ab + q * 2 + 1],  ah, bh + 2);
            mma_f16(corr1[ab + q * 2 + 1], ah, bl + 2);
            mma_f16(corr1[ab + q * 2 + 1], al, bh + 2);
        }
        __syncthreads();
    }
    #undef STAGEW2

    // ---- stage-1 epilogue: +corr, +b2, split G -> H2; u -> cols 256..271 ----
    {
        const int rA = wm * 16 + g, rB = rA + 8;
        #pragma unroll
        for (int b = 0; b < 2; b++) {
            #pragma unroll
            for (int nt = 0; nt < 8; nt++) {
                addcorr(acc1[b * 8 + nt], corr1[b * 8 + nt]);
                int c = (2 * wn + b) * 64 + nt * 8 + t4 * 2;
                float2 bv = __ldg((const float2*)&b2g[c]);
                float v0 = acc1[b * 8 + nt][0] + bv.x, v1 = acc1[b * 8 + nt][1] + bv.y;
                float v2 = acc1[b * 8 + nt][2] + bv.x, v3 = acc1[b * 8 + nt][3] + bv.y;
                __half x0, y0, x1, y1, x2, y2, x3, y3;
                splith(v0, x0, y0); splith(v1, x1, y1); splith(v2, x2, y2); splith(v3, x3, y3);
                *(uint32_t*)(sm + rA * HSTR + c * 2)      = packh(x0, x1);
                *(uint32_t*)(sm + HP + rA * HSTR + c * 2) = packh(y0, y1);
                *(uint32_t*)(sm + rB * HSTR + c * 2)      = packh(x2, x3);
                *(uint32_t*)(sm + HP + rB * HSTR + c * 2) = packh(y2, y3);
            }
        }
        for (int idx = tid; idx < TM * UD; idx += 256) {
            int m = idx >> 4, cu = idx & 15;
            __half hi, lo; splith(su[m * UD + cu], hi, lo);
            *(__half*)(sm + m * HSTR + 512 + cu * 2)      = hi;
            *(__half*)(sm + HP + m * HSTR + 512 + cu * 2) = lo;
        }
    }
    __syncthreads();

    // ================= stage-2: [z|yt][64][288] = [G|u][64][272] x B3^T =================
    float acc2[18][4];
    uint32_t corr2[18][2];
    #pragma unroll
    for (int i = 0; i < 18; i++) {
        acc2[i][0] = acc2[i][1] = acc2[i][2] = acc2[i][3] = 0.f;
        corr2[i][0] = corr2[i][1] = 0u;
    }

    #define STAGE3(kc_, buf_) do { \
        int _kc = (kc_), _bf = (buf_); \
        for (int idx = tid; idx < 1152; idx += 256) { \
            int pl = idx / 576, rem = idx % 576, n = rem >> 1, h16 = rem & 1; \
            const __half* src = (pl ? g_B3l : g_B3h) + (size_t)n * K3 + _kc * 16 + h16 * 8; \
            uint32_t dst = smb + OFF_BB + _bf * BBUF + pl * BPL + n * 48 + h16 * 16; \
            CPA(dst, src); \
        } \
    } while (0)

    STAGE3(0, 0); CPC();
    for (int kc = 0; kc < 17; kc++) {
        if (kc < 16) { STAGE3(kc + 1, (kc + 1) & 1); CPC(); CPW1(); } else { CPW0(); }
        __syncthreads();
        const int buf = kc & 1;
        uint32_t ah[4], al[4];
        uint32_t aaddr = smb + (wm * 16 + aRow) * HSTR + kc * 32 + aCh;
        LDSM4(ah, aaddr); LDSM4(al, aaddr + HP);
        uint32_t bbase = smb + OFF_BB + buf * BBUF + (wn * 144 + bRow) * 48 + bCh;
        #pragma unroll
        for (int q = 0; q < 9; q++) {
            uint32_t bh[4], bl[4];
            uint32_t ba = bbase + q * (16 * 48);
            LDSM4(bh, ba); LDSM4(bl, ba + BPL);
            mma_f32(acc2[q * 2],      ah, bh);
            mma_f16(corr2[q * 2],     ah, bl);
            mma_f16(corr2[q * 2],     al, bh);
            mma_f32(acc2[q * 2 + 1],  ah, bh + 2);
            mma_f16(corr2[q * 2 + 1], ah, bl + 2);
            mma_f16(corr2[q * 2 + 1], al, bh + 2);
        }
        __syncthreads();
    }
    #undef STAGE3

    // ---- epilogue: write z_next and yt (biases fully folded) ----
    float* out_yt = out + (size_t)BSZ * Dd;
    #pragma unroll
    for (int nt = 0; nt < 18; nt++) {
        addcorr(acc2[nt], corr2[nt]);
        const int n0 = wn * 144 + nt * 8 + t4 * 2;
        const int r = wm * 16 + g;
        float v0 = acc2[nt][0], v1 = acc2[nt][1];
        float v2 = acc2[nt][2], v3 = acc2[nt][3];
        if (n0 < Dd) {
            *(float2*)&out[(size_t)(row0 + r) * Dd + n0]     = make_float2(v0, v1);
            *(float2*)&out[(size_t)(row0 + r + 8) * Dd + n0] = make_float2(v2, v3);
        } else {
            const int o = n0 - Dd;
            if (o < NOBS)     { out_yt[(size_t)(row0 + r) * NOBS + o]     = v0;
                                out_yt[(size_t)(row0 + r + 8) * NOBS + o] = v2; }
            if (o + 1 < NOBS) { out_yt[(size_t)(row0 + r) * NOBS + o + 1]     = v1;
                                out_yt[(size_t)(row0 + r + 8) * NOBS + o + 1] = v3; }
        }
    }
}

extern "C" void kernel_launch(void* const* d_in, const int* in_sizes, int n_in,
                              void* d_out, int out_size) {
    const float* z_dyn    = (const float*)d_in[0];
    const float* z_static = (const float*)d_in[1];
    const float* dt       = (const float*)d_in[2];
    const float* ut       = (const float*)d_in[3];
    const float* gates    = (const float*)d_in[4];
    const float* W1       = (const float*)d_in[5];
    const float* b1       = (const float*)d_in[6];
    const float* gamma    = (const float*)d_in[7];
    const float* beta     = (const float*)d_in[8];
    const float* W2       = (const float*)d_in[9];
    const float* b2       = (const float*)d_in[10];
    const float* Bmat     = (const float*)d_in[13];
    const float* Wout     = (const float*)d_in[14];
    const float* Cmat     = (const float*)d_in[15];
    const float* Dm       = (const float*)d_in[16];
    float* out = (float*)d_out;

    preK<<<1040 + NOBS + 8, 256>>>(W1, gates, W2, Wout, Bmat, Cmat, Dm);

    cudaFuncSetAttribute(skolr5, cudaFuncAttributeMaxDynamicSharedMemorySize, SMEM_TOTAL);
    skolr5<<<BSZ / TM, 256, SMEM_TOTAL>>>(z_dyn, z_static, dt, ut, b1, gamma, beta, b2, out);
}